// round 13
// baseline (speedup 1.0000x reference)
#include <cuda_runtime.h>

#define NN 262144
#define NE 1048576
#define NG 8192
#define U  64
#define AD 8
#define DN 512

typedef unsigned long long ull;

// ------------------- scratch (device globals: no allocations allowed) -----
__device__ float g_t[NN * U];         // transformed features t = h @ W + b
__device__ float g_h[NN * U];         // hidden features h
__device__ float g_deg[NN];           // degree + 1 (self loop)
__device__ int   g_degcnt[NN];        // in-degree counts
__device__ int   g_fill[NN];          // CSR fill cursors
__device__ int   g_rowptr[NN + 1];    // CSR row pointers (by dst)
__device__ int   g_bsum[512];         // scan block sums
__device__ int   g_boff[512];         // scan block offsets
__device__ int2  g_csr[NE];           // CSR: (src, norm-as-int) packed per slot
__device__ float g_r[NG * (U + AD)];  // readout + adduct concat
__device__ float g_x1[NG * DN];
__device__ float g_x2[NG * DN];

// ------------------- packed fp32x2 helpers (Blackwell) --------------------
__device__ __forceinline__ ull pk(float a, float b) {
    ull r; asm("mov.b64 %0,{%1,%2};" : "=l"(r) : "f"(a), "f"(b)); return r;
}
__device__ __forceinline__ void fma2(ull& d, ull a, ull b) {
    asm("fma.rn.f32x2 %0,%1,%2,%0;" : "+l"(d) : "l"(a), "l"(b));
}
__device__ __forceinline__ float2 upk(ull v) {
    float2 r; asm("mov.b64 {%0,%1},%2;" : "=f"(r.x), "=f"(r.y) : "l"(v)); return r;
}

// ------------------- CSR construction --------------------------------------
__global__ void k_hist(const int* __restrict__ dst) {
    int e = blockIdx.x * 512 + threadIdx.x;
    atomicAdd(&g_degcnt[dst[e]], 1);
}

__global__ void k_scanA() {
    __shared__ int s[512];
    int t = threadIdx.x;
    s[t] = g_degcnt[blockIdx.x * 512 + t];
    __syncthreads();
    for (int o = 256; o; o >>= 1) { if (t < o) s[t] += s[t + o]; __syncthreads(); }
    if (!t) g_bsum[blockIdx.x] = s[0];
}

__global__ void k_scanB() {
    __shared__ int s[512];
    int t = threadIdx.x;
    int v = g_bsum[t];
    s[t] = v; __syncthreads();
    for (int o = 1; o < 512; o <<= 1) {
        int x = s[t]; if (t >= o) x += s[t - o];
        __syncthreads(); s[t] = x; __syncthreads();
    }
    g_boff[t] = s[t] - v;           // exclusive
    if (!t) g_rowptr[NN] = NE;
}

__global__ void k_scanC() {
    __shared__ int s[512];
    int t = threadIdx.x;
    int i = blockIdx.x * 512 + t;
    int c = g_degcnt[i];
    s[t] = c; __syncthreads();
    for (int o = 1; o < 512; o <<= 1) {
        int x = s[t]; if (t >= o) x += s[t - o];
        __syncthreads(); s[t] = x; __syncthreads();
    }
    g_rowptr[i] = g_boff[blockIdx.x] + s[t] - c;   // exclusive prefix
    g_deg[i] = (float)c + 1.0f;                    // self loop
    g_fill[i] = 0;
}

__global__ void k_fill(const int* __restrict__ src, const int* __restrict__ dst) {
    int e = blockIdx.x * 512 + threadIdx.x;
    int d = dst[e], sc = src[e];
    int pos = atomicAdd(&g_fill[d], 1);
    int slot = g_rowptr[d] + pos;
    float nm = rsqrtf(g_deg[sc] * g_deg[d]);
    g_csr[slot] = make_int2(sc, __float_as_int(nm));
}

// ------------------- adduct copy into g_r tail ------------------------------
__global__ void k_adduct(const float* __restrict__ xadd) {
    int i = blockIdx.x * 256 + threadIdx.x;   // i over NG*AD
    int g = i >> 3, col = i & 7;
    g_r[g * (U + AD) + U + col] = xadd[i];
}

// ------------------- GCN GEMM: t = h @ W + b  (f32x2) ----------------------
__global__ __launch_bounds__(256) void k_gemm(const float* __restrict__ hin_ext,
                                              const float* __restrict__ W,
                                              const float* __restrict__ bias) {
    __shared__ __align__(16) float sW[U * U];
    __shared__ __align__(16) float sB[U];
    const float* hin = hin_ext ? hin_ext : g_h;
    int tid = threadIdx.x;
    {
        const float4* W4 = (const float4*)W;
        float4* s4 = (float4*)sW;
        #pragma unroll
        for (int i = 0; i < 4; i++) s4[tid + i * 256] = W4[tid + i * 256];
        if (tid < 16) ((float4*)sB)[tid] = ((const float4*)bias)[tid];
    }
    __syncthreads();

    int c = tid & 3;            // col group: cols c*16 .. c*16+15
    int g = tid >> 2;           // 0..63
    int row0 = blockIdx.x * 256 + g * 4;

    ull acc[4][8];
    #pragma unroll
    for (int j = 0; j < 8; j++) {
        ull bp = pk(sB[c * 16 + 2 * j], sB[c * 16 + 2 * j + 1]);
        #pragma unroll
        for (int r = 0; r < 4; r++) acc[r][j] = bp;
    }

    const float4* h4 = (const float4*)hin;
    for (int k0 = 0; k0 < 16; k0++) {
        float4 hv[4];
        #pragma unroll
        for (int r = 0; r < 4; r++) hv[r] = h4[(row0 + r) * 16 + k0];
        #pragma unroll
        for (int kk = 0; kk < 4; kk++) {
            const ull* wr = (const ull*)(sW + (k0 * 4 + kk) * U + c * 16);
            ull wp[8];
            #pragma unroll
            for (int j = 0; j < 8; j++) wp[j] = wr[j];
            #pragma unroll
            for (int r = 0; r < 4; r++) {
                float hs = (kk == 0) ? hv[r].x : (kk == 1) ? hv[r].y
                         : (kk == 2) ? hv[r].z : hv[r].w;
                ull hp = pk(hs, hs);
                #pragma unroll
                for (int j = 0; j < 8; j++) fma2(acc[r][j], hp, wp[j]);
            }
        }
    }

    float4* o4 = (float4*)g_t;
    #pragma unroll
    for (int r = 0; r < 4; r++) {
        #pragma unroll
        for (int q = 0; q < 4; q++) {
            float2 p0 = upk(acc[r][2 * q]), p1 = upk(acc[r][2 * q + 1]);
            float4 o; o.x = p0.x; o.y = p0.y; o.z = p1.x; o.w = p1.y;
            o4[(row0 + r) * 16 + c * 4 + q] = o;
        }
    }
}

// ------------------- aggregation (CSR gather, software-pipelined) ----------
// 16 lanes per node, each lane owns a float4 of the 64-wide feature row.
// LAST layer fuses relu + readout scatter, skipping the g_h round-trip.
template <bool LAST>
__global__ __launch_bounds__(256) void k_agg(const int* __restrict__ gid) {
    int tid = threadIdx.x;
    int v = blockIdx.x * 16 + (tid >> 4);
    int lane = tid & 15;
    const float4* t4 = (const float4*)g_t;
    float4 a = t4[v * 16 + lane];
    float inv = 1.0f / g_deg[v];                 // self-loop norm = 1/deg
    a.x *= inv; a.y *= inv; a.z *= inv; a.w *= inv;
    int s = g_rowptr[v], e = g_rowptr[v + 1];

    int2 pr;
    if (s < e) pr = g_csr[s];                    // prime the pipeline
    for (int i = s; i < e; i++) {
        int u = pr.x;
        float nm = __int_as_float(pr.y);
        if (i + 1 < e) pr = g_csr[i + 1];        // prefetch next edge record
        float4 tv = t4[u * 16 + lane];
        a.x += tv.x * nm; a.y += tv.y * nm; a.z += tv.z * nm; a.w += tv.w * nm;
    }
    float hx = fmaxf(a.x, 0.f), hy = fmaxf(a.y, 0.f);
    float hz = fmaxf(a.z, 0.f), hw = fmaxf(a.w, 0.f);

    if (LAST) {
        int g = gid[v];
        float* d = &g_r[g * (U + AD) + lane * 4];
        atomicAdd(d + 0, hx); atomicAdd(d + 1, hy);
        atomicAdd(d + 2, hz); atomicAdd(d + 3, hw);
    } else {
        float4 h; h.x = hx; h.y = hy; h.z = hz; h.w = hw;
        ((float4*)g_h)[v * 16 + lane] = h;
    }
}

// ------------------- dense1: [8192,72]@[72,512] + relu ---------------------
__global__ __launch_bounds__(256) void k_d1(const float* __restrict__ W,
                                            const float* __restrict__ b) {
    __shared__ float rs[64 * 72];
    int tid = threadIdx.x;
    int rb = blockIdx.x >> 2, cb = blockIdx.x & 3;
    int gb = rb * 64, cbase = cb * 128;
    for (int i = tid; i < 64 * 72; i += 256) rs[i] = g_r[gb * 72 + i];
    __syncthreads();
    int rg = tid >> 5, cg = tid & 31;
    int col = cbase + cg * 4;
    float4 bb = *(const float4*)(b + col);
    float acc[8][4] = {};
    for (int k = 0; k < 72; k++) {
        float4 w = *(const float4*)(W + k * DN + col);
        #pragma unroll
        for (int r = 0; r < 8; r++) {
            float a = rs[(rg * 8 + r) * 72 + k];
            acc[r][0] += a * w.x; acc[r][1] += a * w.y;
            acc[r][2] += a * w.z; acc[r][3] += a * w.w;
        }
    }
    #pragma unroll
    for (int r = 0; r < 8; r++) {
        float4 o;
        o.x = fmaxf(acc[r][0] + bb.x, 0.f);
        o.y = fmaxf(acc[r][1] + bb.y, 0.f);
        o.z = fmaxf(acc[r][2] + bb.z, 0.f);
        o.w = fmaxf(acc[r][3] + bb.w, 0.f);
        *(float4*)(g_x1 + (gb + rg * 8 + r) * DN + col) = o;
    }
}

// ------------------- dense2: [8192,512]@[512,512] + relu -------------------
// 128x128 tile, BK=16, 256 threads, 8x8 micro-tile, double-buffered smem.
__global__ __launch_bounds__(256) void k_d2(const float* __restrict__ W,
                                            const float* __restrict__ b) {
    __shared__ __align__(16) float sA[2][16 * 132];   // [k][row], padded
    __shared__ __align__(16) float sB[2][16 * 128];   // [k][col]
    int tid = threadIdx.x;
    int rb = blockIdx.x >> 2, cb = blockIdx.x & 3;
    int row0 = rb * 128, col0 = cb * 128;
    int ty = tid >> 4, tx = tid & 15;

    // loader lane mapping (2 vec4 loads each for A and B)
    int ar0 = tid >> 2,        ac0 = tid & 3;
    int ar1 = (tid + 256) >> 2, ac1 = (tid + 256) & 3;
    int br0 = tid >> 5,        bc0 = tid & 31;
    int br1 = (tid + 256) >> 5, bc1 = (tid + 256) & 31;

    ull acc[8][4];
    #pragma unroll
    for (int j = 0; j < 4; j++) {
        ull bp = pk(b[col0 + tx * 8 + 2 * j], b[col0 + tx * 8 + 2 * j + 1]);
        #pragma unroll
        for (int r = 0; r < 8; r++) acc[r][j] = bp;
    }

    // preload tile 0
    float4 va0 = *(const float4*)(g_x1 + (row0 + ar0) * DN + ac0 * 4);
    float4 va1 = *(const float4*)(g_x1 + (row0 + ar1) * DN + ac1 * 4);
    float4 vb0 = *(const float4*)(W + br0 * DN + col0 + bc0 * 4);
    float4 vb1 = *(const float4*)(W + br1 * DN + col0 + bc1 * 4);
    {
        float* A = sA[0];
        A[(ac0 * 4 + 0) * 132 + ar0] = va0.x; A[(ac0 * 4 + 1) * 132 + ar0] = va0.y;
        A[(ac0 * 4 + 2) * 132 + ar0] = va0.z; A[(ac0 * 4 + 3) * 132 + ar0] = va0.w;
        A[(ac1 * 4 + 0) * 132 + ar1] = va1.x; A[(ac1 * 4 + 1) * 132 + ar1] = va1.y;
        A[(ac1 * 4 + 2) * 132 + ar1] = va1.z; A[(ac1 * 4 + 3) * 132 + ar1] = va1.w;
        *(float4*)(sB[0] + br0 * 128 + bc0 * 4) = vb0;
        *(float4*)(sB[0] + br1 * 128 + bc1 * 4) = vb1;
    }
    __syncthreads();

    for (int kt = 0; kt < 32; kt++) {
        int cur = kt & 1, nxt = cur ^ 1;
        if (kt + 1 < 32) {                         // issue next-tile loads early
            int kb = (kt + 1) * 16;
            va0 = *(const float4*)(g_x1 + (row0 + ar0) * DN + kb + ac0 * 4);
            va1 = *(const float4*)(g_x1 + (row0 + ar1) * DN + kb + ac1 * 4);
            vb0 = *(const float4*)(W + (kb + br0) * DN + col0 + bc0 * 4);
            vb1 = *(const float4*)(W + (kb + br1) * DN + col0 + bc1 * 4);
        }
        const float* A = sA[cur];
        const float* B = sB[cur];
        #pragma unroll
        for (int k = 0; k < 16; k++) {
            float4 a0 = *(const float4*)(A + k * 132 + ty * 8);
            float4 a1 = *(const float4*)(A + k * 132 + ty * 8 + 4);
            const ull* bp = (const ull*)(B + k * 128 + tx * 8);
            ull w0 = bp[0], w1 = bp[1], w2 = bp[2], w3 = bp[3];
            float av[8] = {a0.x, a0.y, a0.z, a0.w, a1.x, a1.y, a1.z, a1.w};
            #pragma unroll
            for (int r = 0; r < 8; r++) {
                ull hp = pk(av[r], av[r]);
                fma2(acc[r][0], hp, w0); fma2(acc[r][1], hp, w1);
                fma2(acc[r][2], hp, w2); fma2(acc[r][3], hp, w3);
            }
        }
        if (kt + 1 < 32) {                         // stage next tile
            float* An = sA[nxt];
            An[(ac0 * 4 + 0) * 132 + ar0] = va0.x; An[(ac0 * 4 + 1) * 132 + ar0] = va0.y;
            An[(ac0 * 4 + 2) * 132 + ar0] = va0.z; An[(ac0 * 4 + 3) * 132 + ar0] = va0.w;
            An[(ac1 * 4 + 0) * 132 + ar1] = va1.x; An[(ac1 * 4 + 1) * 132 + ar1] = va1.y;
            An[(ac1 * 4 + 2) * 132 + ar1] = va1.z; An[(ac1 * 4 + 3) * 132 + ar1] = va1.w;
            *(float4*)(sB[nxt] + br0 * 128 + bc0 * 4) = vb0;
            *(float4*)(sB[nxt] + br1 * 128 + bc1 * 4) = vb1;
        }
        __syncthreads();
    }

    #pragma unroll
    for (int r = 0; r < 8; r++) {
        float2 p0 = upk(acc[r][0]), p1 = upk(acc[r][1]);
        float2 p2 = upk(acc[r][2]), p3 = upk(acc[r][3]);
        float4 o0, o1;
        o0.x = fmaxf(p0.x, 0.f); o0.y = fmaxf(p0.y, 0.f);
        o0.z = fmaxf(p1.x, 0.f); o0.w = fmaxf(p1.y, 0.f);
        o1.x = fmaxf(p2.x, 0.f); o1.y = fmaxf(p2.y, 0.f);
        o1.z = fmaxf(p3.x, 0.f); o1.w = fmaxf(p3.y, 0.f);
        int row = row0 + ty * 8 + r;
        *(float4*)(g_x2 + row * DN + col0 + tx * 8) = o0;
        *(float4*)(g_x2 + row * DN + col0 + tx * 8 + 4) = o1;
    }
}

// ------------------- output head: [8192,512]@[512,1] -----------------------
__global__ void k_out(const float* __restrict__ W, const float* __restrict__ b,
                      float* __restrict__ out) {
    int g = blockIdx.x * 8 + (threadIdx.x >> 5);
    int lane = threadIdx.x & 31;
    const float4* x4 = (const float4*)(g_x2 + g * DN);
    const float4* w4 = (const float4*)W;
    float s = 0.f;
    #pragma unroll
    for (int i = 0; i < 4; i++) {
        float4 x = x4[lane + i * 32], w = w4[lane + i * 32];
        s += x.x * w.x + x.y * w.y + x.z * w.z + x.w * w.w;
    }
    #pragma unroll
    for (int o = 16; o; o >>= 1) s += __shfl_xor_sync(0xffffffffu, s, o);
    if (lane == 0) out[g] = s + b[0];
}

// ------------------- launch -------------------------------------------------
extern "C" void kernel_launch(void* const* d_in, const int* in_sizes, int n_in,
                              void* d_out, int out_size) {
    const float* x_mol = (const float*)d_in[0];
    const float* x_add = (const float*)d_in[1];
    const int*   esrc  = (const int*)d_in[2];
    const int*   edst  = (const int*)d_in[3];
    const int*   gid   = (const int*)d_in[4];
    const float* gW    = (const float*)d_in[5];
    const float* gb    = (const float*)d_in[6];
    const float* d1W   = (const float*)d_in[7];
    const float* d1b   = (const float*)d_in[8];
    const float* d2W   = (const float*)d_in[9];
    const float* d2b   = (const float*)d_in[10];
    const float* oW    = (const float*)d_in[11];
    const float* ob    = (const float*)d_in[12];
    float* out = (float*)d_out;

    void* p_degcnt = nullptr; void* p_r = nullptr;
    cudaGetSymbolAddress(&p_degcnt, g_degcnt);
    cudaGetSymbolAddress(&p_r, g_r);

    // CSR build (degrees + norms reused across all 3 GNN layers)
    cudaMemsetAsync(p_degcnt, 0, NN * sizeof(int));
    k_hist<<<2048, 512>>>(edst);
    k_scanA<<<512, 512>>>();
    k_scanB<<<1, 512>>>();
    k_scanC<<<512, 512>>>();
    k_fill<<<2048, 512>>>(esrc, edst);

    // readout buffer: zeros + adduct tail (layer-3 agg scatters into it)
    cudaMemsetAsync(p_r, 0, NG * (U + AD) * sizeof(float));
    k_adduct<<<NG * AD / 256, 256>>>(x_add);

    // 3 GCN layers: transform (GEMM) then gather-aggregate (no atomics)
    k_gemm<<<NN / 256, 256>>>(x_mol, gW + 0 * U * U, gb + 0 * U);
    k_agg<false><<<NN / 16, 256>>>(gid);
    k_gemm<<<NN / 256, 256>>>(nullptr, gW + 1 * U * U, gb + 1 * U);
    k_agg<false><<<NN / 16, 256>>>(gid);
    k_gemm<<<NN / 256, 256>>>(nullptr, gW + 2 * U * U, gb + 2 * U);
    k_agg<true><<<NN / 16, 256>>>(gid);   // fused relu + readout scatter

    // MLP head
    k_d1<<<512, 256>>>(d1W, d1b);
    k_d2<<<256, 256>>>(d2W, d2b);
    k_out<<<NG / 8, 256>>>(oW, ob, out);
}

// round 14
// speedup vs baseline: 1.0018x; 1.0018x over previous
#include <cuda_runtime.h>

#define NN 262144
#define NE 1048576
#define NG 8192
#define U  64
#define AD 8
#define DN 512

typedef unsigned long long ull;

// ------------------- scratch (device globals: no allocations allowed) -----
__device__ float g_t[NN * U];         // transformed features t = h @ W + b
__device__ float g_h[NN * U];         // hidden features h
__device__ float g_deg[NN];           // degree + 1 (self loop)
__device__ int   g_degcnt[NN];        // in-degree counts
__device__ int   g_fill[NN];          // CSR fill cursors
__device__ int   g_rowptr[NN + 1];    // CSR row pointers (by dst)
__device__ int   g_bsum[512];         // scan block sums
__device__ int   g_boff[512];         // scan block offsets
__device__ int2  g_csr[NE];           // CSR: (src, norm-as-int) packed per slot
__device__ float g_r[NG * (U + AD)];  // readout + adduct concat
__device__ float g_x1[NG * DN];
__device__ float g_x2[NG * DN];

// ------------------- packed fp32x2 helpers (Blackwell) --------------------
__device__ __forceinline__ ull pk(float a, float b) {
    ull r; asm("mov.b64 %0,{%1,%2};" : "=l"(r) : "f"(a), "f"(b)); return r;
}
__device__ __forceinline__ void fma2(ull& d, ull a, ull b) {
    asm("fma.rn.f32x2 %0,%1,%2,%0;" : "+l"(d) : "l"(a), "l"(b));
}
__device__ __forceinline__ float2 upk(ull v) {
    float2 r; asm("mov.b64 {%0,%1},%2;" : "=f"(r.x), "=f"(r.y) : "l"(v)); return r;
}

// ------------------- CSR construction --------------------------------------
__global__ void k_hist(const int* __restrict__ dst) {
    int e = blockIdx.x * 512 + threadIdx.x;
    atomicAdd(&g_degcnt[dst[e]], 1);
}

__global__ void k_scanA() {
    __shared__ int s[512];
    int t = threadIdx.x;
    s[t] = g_degcnt[blockIdx.x * 512 + t];
    __syncthreads();
    for (int o = 256; o; o >>= 1) { if (t < o) s[t] += s[t + o]; __syncthreads(); }
    if (!t) g_bsum[blockIdx.x] = s[0];
}

__global__ void k_scanB() {
    __shared__ int s[512];
    int t = threadIdx.x;
    int v = g_bsum[t];
    s[t] = v; __syncthreads();
    for (int o = 1; o < 512; o <<= 1) {
        int x = s[t]; if (t >= o) x += s[t - o];
        __syncthreads(); s[t] = x; __syncthreads();
    }
    g_boff[t] = s[t] - v;           // exclusive
    if (!t) g_rowptr[NN] = NE;
}

__global__ void k_scanC() {
    __shared__ int s[512];
    int t = threadIdx.x;
    int i = blockIdx.x * 512 + t;
    int c = g_degcnt[i];
    s[t] = c; __syncthreads();
    for (int o = 1; o < 512; o <<= 1) {
        int x = s[t]; if (t >= o) x += s[t - o];
        __syncthreads(); s[t] = x; __syncthreads();
    }
    g_rowptr[i] = g_boff[blockIdx.x] + s[t] - c;   // exclusive prefix
    g_deg[i] = (float)c + 1.0f;                    // self loop
    g_fill[i] = 0;
}

__global__ void k_fill(const int* __restrict__ src, const int* __restrict__ dst) {
    int e = blockIdx.x * 512 + threadIdx.x;
    int d = dst[e], sc = src[e];
    int pos = atomicAdd(&g_fill[d], 1);
    int slot = g_rowptr[d] + pos;
    float nm = rsqrtf(g_deg[sc] * g_deg[d]);
    g_csr[slot] = make_int2(sc, __float_as_int(nm));
}

// ------------------- adduct copy into g_r tail ------------------------------
__global__ void k_adduct(const float* __restrict__ xadd) {
    int i = blockIdx.x * 256 + threadIdx.x;   // i over NG*AD
    int g = i >> 3, col = i & 7;
    g_r[g * (U + AD) + U + col] = xadd[i];
}

// ------------------- GCN GEMM: t = h @ W + b  (f32x2) ----------------------
__global__ __launch_bounds__(256) void k_gemm(const float* __restrict__ hin_ext,
                                              const float* __restrict__ W,
                                              const float* __restrict__ bias) {
    __shared__ __align__(16) float sW[U * U];
    __shared__ __align__(16) float sB[U];
    const float* hin = hin_ext ? hin_ext : g_h;
    int tid = threadIdx.x;
    {
        const float4* W4 = (const float4*)W;
        float4* s4 = (float4*)sW;
        #pragma unroll
        for (int i = 0; i < 4; i++) s4[tid + i * 256] = W4[tid + i * 256];
        if (tid < 16) ((float4*)sB)[tid] = ((const float4*)bias)[tid];
    }
    __syncthreads();

    int c = tid & 3;            // col group: cols c*16 .. c*16+15
    int g = tid >> 2;           // 0..63
    int row0 = blockIdx.x * 256 + g * 4;

    ull acc[4][8];
    #pragma unroll
    for (int j = 0; j < 8; j++) {
        ull bp = pk(sB[c * 16 + 2 * j], sB[c * 16 + 2 * j + 1]);
        #pragma unroll
        for (int r = 0; r < 4; r++) acc[r][j] = bp;
    }

    const float4* h4 = (const float4*)hin;
    for (int k0 = 0; k0 < 16; k0++) {
        float4 hv[4];
        #pragma unroll
        for (int r = 0; r < 4; r++) hv[r] = h4[(row0 + r) * 16 + k0];
        #pragma unroll
        for (int kk = 0; kk < 4; kk++) {
            const ull* wr = (const ull*)(sW + (k0 * 4 + kk) * U + c * 16);
            ull wp[8];
            #pragma unroll
            for (int j = 0; j < 8; j++) wp[j] = wr[j];
            #pragma unroll
            for (int r = 0; r < 4; r++) {
                float hs = (kk == 0) ? hv[r].x : (kk == 1) ? hv[r].y
                         : (kk == 2) ? hv[r].z : hv[r].w;
                ull hp = pk(hs, hs);
                #pragma unroll
                for (int j = 0; j < 8; j++) fma2(acc[r][j], hp, wp[j]);
            }
        }
    }

    float4* o4 = (float4*)g_t;
    #pragma unroll
    for (int r = 0; r < 4; r++) {
        #pragma unroll
        for (int q = 0; q < 4; q++) {
            float2 p0 = upk(acc[r][2 * q]), p1 = upk(acc[r][2 * q + 1]);
            float4 o; o.x = p0.x; o.y = p0.y; o.z = p1.x; o.w = p1.y;
            o4[(row0 + r) * 16 + c * 4 + q] = o;
        }
    }
}

// ------------------- aggregation (CSR gather, software-pipelined) ----------
// 16 lanes per node, each lane owns a float4 of the 64-wide feature row.
// LAST layer fuses relu + readout scatter, skipping the g_h round-trip.
template <bool LAST>
__global__ __launch_bounds__(256) void k_agg(const int* __restrict__ gid) {
    int tid = threadIdx.x;
    int v = blockIdx.x * 16 + (tid >> 4);
    int lane = tid & 15;
    const float4* t4 = (const float4*)g_t;
    float4 a = t4[v * 16 + lane];
    float inv = 1.0f / g_deg[v];                 // self-loop norm = 1/deg
    a.x *= inv; a.y *= inv; a.z *= inv; a.w *= inv;
    int s = g_rowptr[v], e = g_rowptr[v + 1];

    int2 pr;
    if (s < e) pr = g_csr[s];                    // prime the pipeline
    for (int i = s; i < e; i++) {
        int u = pr.x;
        float nm = __int_as_float(pr.y);
        if (i + 1 < e) pr = g_csr[i + 1];        // prefetch next edge record
        float4 tv = t4[u * 16 + lane];
        a.x += tv.x * nm; a.y += tv.y * nm; a.z += tv.z * nm; a.w += tv.w * nm;
    }
    float hx = fmaxf(a.x, 0.f), hy = fmaxf(a.y, 0.f);
    float hz = fmaxf(a.z, 0.f), hw = fmaxf(a.w, 0.f);

    if (LAST) {
        int g = gid[v];
        float* d = &g_r[g * (U + AD) + lane * 4];
        atomicAdd(d + 0, hx); atomicAdd(d + 1, hy);
        atomicAdd(d + 2, hz); atomicAdd(d + 3, hw);
    } else {
        float4 h; h.x = hx; h.y = hy; h.z = hz; h.w = hw;
        ((float4*)g_h)[v * 16 + lane] = h;
    }
}

// ------------------- dense1: [8192,72]@[72,512] + relu ---------------------
__global__ __launch_bounds__(256) void k_d1(const float* __restrict__ W,
                                            const float* __restrict__ b) {
    __shared__ float rs[64 * 72];
    int tid = threadIdx.x;
    int rb = blockIdx.x >> 2, cb = blockIdx.x & 3;
    int gb = rb * 64, cbase = cb * 128;
    for (int i = tid; i < 64 * 72; i += 256) rs[i] = g_r[gb * 72 + i];
    __syncthreads();
    int rg = tid >> 5, cg = tid & 31;
    int col = cbase + cg * 4;
    float4 bb = *(const float4*)(b + col);
    float acc[8][4] = {};
    for (int k = 0; k < 72; k++) {
        float4 w = *(const float4*)(W + k * DN + col);
        #pragma unroll
        for (int r = 0; r < 8; r++) {
            float a = rs[(rg * 8 + r) * 72 + k];
            acc[r][0] += a * w.x; acc[r][1] += a * w.y;
            acc[r][2] += a * w.z; acc[r][3] += a * w.w;
        }
    }
    #pragma unroll
    for (int r = 0; r < 8; r++) {
        float4 o;
        o.x = fmaxf(acc[r][0] + bb.x, 0.f);
        o.y = fmaxf(acc[r][1] + bb.y, 0.f);
        o.z = fmaxf(acc[r][2] + bb.z, 0.f);
        o.w = fmaxf(acc[r][3] + bb.w, 0.f);
        *(float4*)(g_x1 + (gb + rg * 8 + r) * DN + col) = o;
    }
}

// ------------------- dense2: [8192,512]@[512,512] + relu -------------------
// 128x128 tile, BK=16, 256 threads, 8x8 micro-tile, double-buffered smem.
__global__ __launch_bounds__(256) void k_d2(const float* __restrict__ W,
                                            const float* __restrict__ b) {
    __shared__ __align__(16) float sA[2][16 * 132];   // [k][row], padded
    __shared__ __align__(16) float sB[2][16 * 128];   // [k][col]
    int tid = threadIdx.x;
    int rb = blockIdx.x >> 2, cb = blockIdx.x & 3;
    int row0 = rb * 128, col0 = cb * 128;
    int ty = tid >> 4, tx = tid & 15;

    // loader lane mapping (2 vec4 loads each for A and B)
    int ar0 = tid >> 2,        ac0 = tid & 3;
    int ar1 = (tid + 256) >> 2, ac1 = (tid + 256) & 3;
    int br0 = tid >> 5,        bc0 = tid & 31;
    int br1 = (tid + 256) >> 5, bc1 = (tid + 256) & 31;

    ull acc[8][4];
    #pragma unroll
    for (int j = 0; j < 4; j++) {
        ull bp = pk(b[col0 + tx * 8 + 2 * j], b[col0 + tx * 8 + 2 * j + 1]);
        #pragma unroll
        for (int r = 0; r < 8; r++) acc[r][j] = bp;
    }

    // preload tile 0
    float4 va0 = *(const float4*)(g_x1 + (row0 + ar0) * DN + ac0 * 4);
    float4 va1 = *(const float4*)(g_x1 + (row0 + ar1) * DN + ac1 * 4);
    float4 vb0 = *(const float4*)(W + br0 * DN + col0 + bc0 * 4);
    float4 vb1 = *(const float4*)(W + br1 * DN + col0 + bc1 * 4);
    {
        float* A = sA[0];
        A[(ac0 * 4 + 0) * 132 + ar0] = va0.x; A[(ac0 * 4 + 1) * 132 + ar0] = va0.y;
        A[(ac0 * 4 + 2) * 132 + ar0] = va0.z; A[(ac0 * 4 + 3) * 132 + ar0] = va0.w;
        A[(ac1 * 4 + 0) * 132 + ar1] = va1.x; A[(ac1 * 4 + 1) * 132 + ar1] = va1.y;
        A[(ac1 * 4 + 2) * 132 + ar1] = va1.z; A[(ac1 * 4 + 3) * 132 + ar1] = va1.w;
        *(float4*)(sB[0] + br0 * 128 + bc0 * 4) = vb0;
        *(float4*)(sB[0] + br1 * 128 + bc1 * 4) = vb1;
    }
    __syncthreads();

    for (int kt = 0; kt < 32; kt++) {
        int cur = kt & 1, nxt = cur ^ 1;
        if (kt + 1 < 32) {                         // issue next-tile loads early
            int kb = (kt + 1) * 16;
            va0 = *(const float4*)(g_x1 + (row0 + ar0) * DN + kb + ac0 * 4);
            va1 = *(const float4*)(g_x1 + (row0 + ar1) * DN + kb + ac1 * 4);
            vb0 = *(const float4*)(W + (kb + br0) * DN + col0 + bc0 * 4);
            vb1 = *(const float4*)(W + (kb + br1) * DN + col0 + bc1 * 4);
        }
        const float* A = sA[cur];
        const float* B = sB[cur];
        #pragma unroll
        for (int k = 0; k < 16; k++) {
            float4 a0 = *(const float4*)(A + k * 132 + ty * 8);
            float4 a1 = *(const float4*)(A + k * 132 + ty * 8 + 4);
            const ull* bp = (const ull*)(B + k * 128 + tx * 8);
            ull w0 = bp[0], w1 = bp[1], w2 = bp[2], w3 = bp[3];
            float av[8] = {a0.x, a0.y, a0.z, a0.w, a1.x, a1.y, a1.z, a1.w};
            #pragma unroll
            for (int r = 0; r < 8; r++) {
                ull hp = pk(av[r], av[r]);
                fma2(acc[r][0], hp, w0); fma2(acc[r][1], hp, w1);
                fma2(acc[r][2], hp, w2); fma2(acc[r][3], hp, w3);
            }
        }
        if (kt + 1 < 32) {                         // stage next tile
            float* An = sA[nxt];
            An[(ac0 * 4 + 0) * 132 + ar0] = va0.x; An[(ac0 * 4 + 1) * 132 + ar0] = va0.y;
            An[(ac0 * 4 + 2) * 132 + ar0] = va0.z; An[(ac0 * 4 + 3) * 132 + ar0] = va0.w;
            An[(ac1 * 4 + 0) * 132 + ar1] = va1.x; An[(ac1 * 4 + 1) * 132 + ar1] = va1.y;
            An[(ac1 * 4 + 2) * 132 + ar1] = va1.z; An[(ac1 * 4 + 3) * 132 + ar1] = va1.w;
            *(float4*)(sB[nxt] + br0 * 128 + bc0 * 4) = vb0;
            *(float4*)(sB[nxt] + br1 * 128 + bc1 * 4) = vb1;
        }
        __syncthreads();
    }

    #pragma unroll
    for (int r = 0; r < 8; r++) {
        float2 p0 = upk(acc[r][0]), p1 = upk(acc[r][1]);
        float2 p2 = upk(acc[r][2]), p3 = upk(acc[r][3]);
        float4 o0, o1;
        o0.x = fmaxf(p0.x, 0.f); o0.y = fmaxf(p0.y, 0.f);
        o0.z = fmaxf(p1.x, 0.f); o0.w = fmaxf(p1.y, 0.f);
        o1.x = fmaxf(p2.x, 0.f); o1.y = fmaxf(p2.y, 0.f);
        o1.z = fmaxf(p3.x, 0.f); o1.w = fmaxf(p3.y, 0.f);
        int row = row0 + ty * 8 + r;
        *(float4*)(g_x2 + row * DN + col0 + tx * 8) = o0;
        *(float4*)(g_x2 + row * DN + col0 + tx * 8 + 4) = o1;
    }
}

// ------------------- output head: [8192,512]@[512,1] -----------------------
__global__ void k_out(const float* __restrict__ W, const float* __restrict__ b,
                      float* __restrict__ out) {
    int g = blockIdx.x * 8 + (threadIdx.x >> 5);
    int lane = threadIdx.x & 31;
    const float4* x4 = (const float4*)(g_x2 + g * DN);
    const float4* w4 = (const float4*)W;
    float s = 0.f;
    #pragma unroll
    for (int i = 0; i < 4; i++) {
        float4 x = x4[lane + i * 32], w = w4[lane + i * 32];
        s += x.x * w.x + x.y * w.y + x.z * w.z + x.w * w.w;
    }
    #pragma unroll
    for (int o = 16; o; o >>= 1) s += __shfl_xor_sync(0xffffffffu, s, o);
    if (lane == 0) out[g] = s + b[0];
}

// ------------------- launch -------------------------------------------------
extern "C" void kernel_launch(void* const* d_in, const int* in_sizes, int n_in,
                              void* d_out, int out_size) {
    const float* x_mol = (const float*)d_in[0];
    const float* x_add = (const float*)d_in[1];
    const int*   esrc  = (const int*)d_in[2];
    const int*   edst  = (const int*)d_in[3];
    const int*   gid   = (const int*)d_in[4];
    const float* gW    = (const float*)d_in[5];
    const float* gb    = (const float*)d_in[6];
    const float* d1W   = (const float*)d_in[7];
    const float* d1b   = (const float*)d_in[8];
    const float* d2W   = (const float*)d_in[9];
    const float* d2b   = (const float*)d_in[10];
    const float* oW    = (const float*)d_in[11];
    const float* ob    = (const float*)d_in[12];
    float* out = (float*)d_out;

    void* p_degcnt = nullptr; void* p_r = nullptr;
    cudaGetSymbolAddress(&p_degcnt, g_degcnt);
    cudaGetSymbolAddress(&p_r, g_r);

    // CSR build (degrees + norms reused across all 3 GNN layers)
    cudaMemsetAsync(p_degcnt, 0, NN * sizeof(int));
    k_hist<<<2048, 512>>>(edst);
    k_scanA<<<512, 512>>>();
    k_scanB<<<1, 512>>>();
    k_scanC<<<512, 512>>>();
    k_fill<<<2048, 512>>>(esrc, edst);

    // readout buffer: zeros + adduct tail (layer-3 agg scatters into it)
    cudaMemsetAsync(p_r, 0, NG * (U + AD) * sizeof(float));
    k_adduct<<<NG * AD / 256, 256>>>(x_add);

    // 3 GCN layers: transform (GEMM) then gather-aggregate (no atomics)
    k_gemm<<<NN / 256, 256>>>(x_mol, gW + 0 * U * U, gb + 0 * U);
    k_agg<false><<<NN / 16, 256>>>(gid);
    k_gemm<<<NN / 256, 256>>>(nullptr, gW + 1 * U * U, gb + 1 * U);
    k_agg<false><<<NN / 16, 256>>>(gid);
    k_gemm<<<NN / 256, 256>>>(nullptr, gW + 2 * U * U, gb + 2 * U);
    k_agg<true><<<NN / 16, 256>>>(gid);   // fused relu + readout scatter

    // MLP head
    k_d1<<<512, 256>>>(d1W, d1b);
    k_d2<<<256, 256>>>(d2W, d2b);
    k_out<<<NG / 8, 256>>>(oW, ob, out);
}

// round 15
// speedup vs baseline: 1.0024x; 1.0006x over previous
#include <cuda_runtime.h>

#define NN 262144
#define NE 1048576
#define NG 8192
#define U  64
#define AD 8
#define DN 512

typedef unsigned long long ull;

// ------------------- scratch (device globals: no allocations allowed) -----
__device__ float g_t[NN * U];         // transformed features t = h @ W + b
__device__ float g_h[NN * U];         // hidden features h
__device__ float g_deg[NN];           // degree + 1 (self loop)
__device__ int   g_degcnt[NN];        // in-degree counts
__device__ int   g_fill[NN];          // CSR fill cursors
__device__ int   g_rowptr[NN + 1];    // CSR row pointers (by dst)
__device__ int   g_bsum[512];         // scan block sums
__device__ int   g_boff[512];         // scan block offsets
__device__ int2  g_csr[NE];           // CSR: (src, norm-as-int) packed per slot
__device__ float g_r[NG * (U + AD)];  // readout + adduct concat
__device__ float g_x1[NG * DN];
__device__ float g_x2[NG * DN];

// ------------------- packed fp32x2 helpers (Blackwell) --------------------
__device__ __forceinline__ ull pk(float a, float b) {
    ull r; asm("mov.b64 %0,{%1,%2};" : "=l"(r) : "f"(a), "f"(b)); return r;
}
__device__ __forceinline__ void fma2(ull& d, ull a, ull b) {
    asm("fma.rn.f32x2 %0,%1,%2,%0;" : "+l"(d) : "l"(a), "l"(b));
}
__device__ __forceinline__ float2 upk(ull v) {
    float2 r; asm("mov.b64 {%0,%1},%2;" : "=f"(r.x), "=f"(r.y) : "l"(v)); return r;
}

// ------------------- CSR construction --------------------------------------
__global__ void k_hist(const int* __restrict__ dst) {
    int e = blockIdx.x * 512 + threadIdx.x;
    atomicAdd(&g_degcnt[dst[e]], 1);
}

__global__ void k_scanA() {
    __shared__ int s[512];
    int t = threadIdx.x;
    s[t] = g_degcnt[blockIdx.x * 512 + t];
    __syncthreads();
    for (int o = 256; o; o >>= 1) { if (t < o) s[t] += s[t + o]; __syncthreads(); }
    if (!t) g_bsum[blockIdx.x] = s[0];
}

__global__ void k_scanB() {
    __shared__ int s[512];
    int t = threadIdx.x;
    int v = g_bsum[t];
    s[t] = v; __syncthreads();
    for (int o = 1; o < 512; o <<= 1) {
        int x = s[t]; if (t >= o) x += s[t - o];
        __syncthreads(); s[t] = x; __syncthreads();
    }
    g_boff[t] = s[t] - v;           // exclusive
    if (!t) g_rowptr[NN] = NE;
}

__global__ void k_scanC() {
    __shared__ int s[512];
    int t = threadIdx.x;
    int i = blockIdx.x * 512 + t;
    int c = g_degcnt[i];
    s[t] = c; __syncthreads();
    for (int o = 1; o < 512; o <<= 1) {
        int x = s[t]; if (t >= o) x += s[t - o];
        __syncthreads(); s[t] = x; __syncthreads();
    }
    g_rowptr[i] = g_boff[blockIdx.x] + s[t] - c;   // exclusive prefix
    g_deg[i] = (float)c + 1.0f;                    // self loop
    g_fill[i] = 0;
}

__global__ void k_fill(const int* __restrict__ src, const int* __restrict__ dst) {
    int e = blockIdx.x * 512 + threadIdx.x;
    int d = dst[e], sc = src[e];
    int pos = atomicAdd(&g_fill[d], 1);
    int slot = g_rowptr[d] + pos;
    float nm = rsqrtf(g_deg[sc] * g_deg[d]);
    g_csr[slot] = make_int2(sc, __float_as_int(nm));
}

// ------------------- adduct copy into g_r tail ------------------------------
__global__ void k_adduct(const float* __restrict__ xadd) {
    int i = blockIdx.x * 256 + threadIdx.x;   // i over NG*AD
    int g = i >> 3, col = i & 7;
    g_r[g * (U + AD) + U + col] = xadd[i];
}

// ------------------- GCN GEMM: t = h @ W + b  (f32x2) ----------------------
__global__ __launch_bounds__(256) void k_gemm(const float* __restrict__ hin_ext,
                                              const float* __restrict__ W,
                                              const float* __restrict__ bias) {
    __shared__ __align__(16) float sW[U * U];
    __shared__ __align__(16) float sB[U];
    const float* hin = hin_ext ? hin_ext : g_h;
    int tid = threadIdx.x;
    {
        const float4* W4 = (const float4*)W;
        float4* s4 = (float4*)sW;
        #pragma unroll
        for (int i = 0; i < 4; i++) s4[tid + i * 256] = W4[tid + i * 256];
        if (tid < 16) ((float4*)sB)[tid] = ((const float4*)bias)[tid];
    }
    __syncthreads();

    int c = tid & 3;            // col group: cols c*16 .. c*16+15
    int g = tid >> 2;           // 0..63
    int row0 = blockIdx.x * 256 + g * 4;

    ull acc[4][8];
    #pragma unroll
    for (int j = 0; j < 8; j++) {
        ull bp = pk(sB[c * 16 + 2 * j], sB[c * 16 + 2 * j + 1]);
        #pragma unroll
        for (int r = 0; r < 4; r++) acc[r][j] = bp;
    }

    const float4* h4 = (const float4*)hin;
    for (int k0 = 0; k0 < 16; k0++) {
        float4 hv[4];
        #pragma unroll
        for (int r = 0; r < 4; r++) hv[r] = h4[(row0 + r) * 16 + k0];
        #pragma unroll
        for (int kk = 0; kk < 4; kk++) {
            const ull* wr = (const ull*)(sW + (k0 * 4 + kk) * U + c * 16);
            ull wp[8];
            #pragma unroll
            for (int j = 0; j < 8; j++) wp[j] = wr[j];
            #pragma unroll
            for (int r = 0; r < 4; r++) {
                float hs = (kk == 0) ? hv[r].x : (kk == 1) ? hv[r].y
                         : (kk == 2) ? hv[r].z : hv[r].w;
                ull hp = pk(hs, hs);
                #pragma unroll
                for (int j = 0; j < 8; j++) fma2(acc[r][j], hp, wp[j]);
            }
        }
    }

    float4* o4 = (float4*)g_t;
    #pragma unroll
    for (int r = 0; r < 4; r++) {
        #pragma unroll
        for (int q = 0; q < 4; q++) {
            float2 p0 = upk(acc[r][2 * q]), p1 = upk(acc[r][2 * q + 1]);
            float4 o; o.x = p0.x; o.y = p0.y; o.z = p1.x; o.w = p1.y;
            o4[(row0 + r) * 16 + c * 4 + q] = o;
        }
    }
}

// ------------------- aggregation (CSR gather, software-pipelined) ----------
// 16 lanes per node, each lane owns a float4 of the 64-wide feature row.
// LAST layer fuses relu + readout scatter, skipping the g_h round-trip.
template <bool LAST>
__global__ __launch_bounds__(256) void k_agg(const int* __restrict__ gid) {
    int tid = threadIdx.x;
    int v = blockIdx.x * 16 + (tid >> 4);
    int lane = tid & 15;
    const float4* t4 = (const float4*)g_t;
    float4 a = t4[v * 16 + lane];
    float inv = 1.0f / g_deg[v];                 // self-loop norm = 1/deg
    a.x *= inv; a.y *= inv; a.z *= inv; a.w *= inv;
    int s = g_rowptr[v], e = g_rowptr[v + 1];

    int2 pr;
    if (s < e) pr = g_csr[s];                    // prime the pipeline
    for (int i = s; i < e; i++) {
        int u = pr.x;
        float nm = __int_as_float(pr.y);
        if (i + 1 < e) pr = g_csr[i + 1];        // prefetch next edge record
        float4 tv = t4[u * 16 + lane];
        a.x += tv.x * nm; a.y += tv.y * nm; a.z += tv.z * nm; a.w += tv.w * nm;
    }
    float hx = fmaxf(a.x, 0.f), hy = fmaxf(a.y, 0.f);
    float hz = fmaxf(a.z, 0.f), hw = fmaxf(a.w, 0.f);

    if (LAST) {
        int g = gid[v];
        float* d = &g_r[g * (U + AD) + lane * 4];
        atomicAdd(d + 0, hx); atomicAdd(d + 1, hy);
        atomicAdd(d + 2, hz); atomicAdd(d + 3, hw);
    } else {
        float4 h; h.x = hx; h.y = hy; h.z = hz; h.w = hw;
        ((float4*)g_h)[v * 16 + lane] = h;
    }
}

// ------------------- dense1: [8192,72]@[72,512] + relu ---------------------
__global__ __launch_bounds__(256) void k_d1(const float* __restrict__ W,
                                            const float* __restrict__ b) {
    __shared__ float rs[64 * 72];
    int tid = threadIdx.x;
    int rb = blockIdx.x >> 2, cb = blockIdx.x & 3;
    int gb = rb * 64, cbase = cb * 128;
    for (int i = tid; i < 64 * 72; i += 256) rs[i] = g_r[gb * 72 + i];
    __syncthreads();
    int rg = tid >> 5, cg = tid & 31;
    int col = cbase + cg * 4;
    float4 bb = *(const float4*)(b + col);
    float acc[8][4] = {};
    for (int k = 0; k < 72; k++) {
        float4 w = *(const float4*)(W + k * DN + col);
        #pragma unroll
        for (int r = 0; r < 8; r++) {
            float a = rs[(rg * 8 + r) * 72 + k];
            acc[r][0] += a * w.x; acc[r][1] += a * w.y;
            acc[r][2] += a * w.z; acc[r][3] += a * w.w;
        }
    }
    #pragma unroll
    for (int r = 0; r < 8; r++) {
        float4 o;
        o.x = fmaxf(acc[r][0] + bb.x, 0.f);
        o.y = fmaxf(acc[r][1] + bb.y, 0.f);
        o.z = fmaxf(acc[r][2] + bb.z, 0.f);
        o.w = fmaxf(acc[r][3] + bb.w, 0.f);
        *(float4*)(g_x1 + (gb + rg * 8 + r) * DN + col) = o;
    }
}

// ------------------- dense2: [8192,512]@[512,512] + relu -------------------
// 128x128 tile, BK=16, 256 threads, 8x8 micro-tile, double-buffered smem.
__global__ __launch_bounds__(256) void k_d2(const float* __restrict__ W,
                                            const float* __restrict__ b) {
    __shared__ __align__(16) float sA[2][16 * 132];   // [k][row], padded
    __shared__ __align__(16) float sB[2][16 * 128];   // [k][col]
    int tid = threadIdx.x;
    int rb = blockIdx.x >> 2, cb = blockIdx.x & 3;
    int row0 = rb * 128, col0 = cb * 128;
    int ty = tid >> 4, tx = tid & 15;

    // loader lane mapping (2 vec4 loads each for A and B)
    int ar0 = tid >> 2,        ac0 = tid & 3;
    int ar1 = (tid + 256) >> 2, ac1 = (tid + 256) & 3;
    int br0 = tid >> 5,        bc0 = tid & 31;
    int br1 = (tid + 256) >> 5, bc1 = (tid + 256) & 31;

    ull acc[8][4];
    #pragma unroll
    for (int j = 0; j < 4; j++) {
        ull bp = pk(b[col0 + tx * 8 + 2 * j], b[col0 + tx * 8 + 2 * j + 1]);
        #pragma unroll
        for (int r = 0; r < 8; r++) acc[r][j] = bp;
    }

    // preload tile 0
    float4 va0 = *(const float4*)(g_x1 + (row0 + ar0) * DN + ac0 * 4);
    float4 va1 = *(const float4*)(g_x1 + (row0 + ar1) * DN + ac1 * 4);
    float4 vb0 = *(const float4*)(W + br0 * DN + col0 + bc0 * 4);
    float4 vb1 = *(const float4*)(W + br1 * DN + col0 + bc1 * 4);
    {
        float* A = sA[0];
        A[(ac0 * 4 + 0) * 132 + ar0] = va0.x; A[(ac0 * 4 + 1) * 132 + ar0] = va0.y;
        A[(ac0 * 4 + 2) * 132 + ar0] = va0.z; A[(ac0 * 4 + 3) * 132 + ar0] = va0.w;
        A[(ac1 * 4 + 0) * 132 + ar1] = va1.x; A[(ac1 * 4 + 1) * 132 + ar1] = va1.y;
        A[(ac1 * 4 + 2) * 132 + ar1] = va1.z; A[(ac1 * 4 + 3) * 132 + ar1] = va1.w;
        *(float4*)(sB[0] + br0 * 128 + bc0 * 4) = vb0;
        *(float4*)(sB[0] + br1 * 128 + bc1 * 4) = vb1;
    }
    __syncthreads();

    for (int kt = 0; kt < 32; kt++) {
        int cur = kt & 1, nxt = cur ^ 1;
        if (kt + 1 < 32) {                         // issue next-tile loads early
            int kb = (kt + 1) * 16;
            va0 = *(const float4*)(g_x1 + (row0 + ar0) * DN + kb + ac0 * 4);
            va1 = *(const float4*)(g_x1 + (row0 + ar1) * DN + kb + ac1 * 4);
            vb0 = *(const float4*)(W + (kb + br0) * DN + col0 + bc0 * 4);
            vb1 = *(const float4*)(W + (kb + br1) * DN + col0 + bc1 * 4);
        }
        const float* A = sA[cur];
        const float* B = sB[cur];
        #pragma unroll
        for (int k = 0; k < 16; k++) {
            float4 a0 = *(const float4*)(A + k * 132 + ty * 8);
            float4 a1 = *(const float4*)(A + k * 132 + ty * 8 + 4);
            const ull* bp = (const ull*)(B + k * 128 + tx * 8);
            ull w0 = bp[0], w1 = bp[1], w2 = bp[2], w3 = bp[3];
            float av[8] = {a0.x, a0.y, a0.z, a0.w, a1.x, a1.y, a1.z, a1.w};
            #pragma unroll
            for (int r = 0; r < 8; r++) {
                ull hp = pk(av[r], av[r]);
                fma2(acc[r][0], hp, w0); fma2(acc[r][1], hp, w1);
                fma2(acc[r][2], hp, w2); fma2(acc[r][3], hp, w3);
            }
        }
        if (kt + 1 < 32) {                         // stage next tile
            float* An = sA[nxt];
            An[(ac0 * 4 + 0) * 132 + ar0] = va0.x; An[(ac0 * 4 + 1) * 132 + ar0] = va0.y;
            An[(ac0 * 4 + 2) * 132 + ar0] = va0.z; An[(ac0 * 4 + 3) * 132 + ar0] = va0.w;
            An[(ac1 * 4 + 0) * 132 + ar1] = va1.x; An[(ac1 * 4 + 1) * 132 + ar1] = va1.y;
            An[(ac1 * 4 + 2) * 132 + ar1] = va1.z; An[(ac1 * 4 + 3) * 132 + ar1] = va1.w;
            *(float4*)(sB[nxt] + br0 * 128 + bc0 * 4) = vb0;
            *(float4*)(sB[nxt] + br1 * 128 + bc1 * 4) = vb1;
        }
        __syncthreads();
    }

    #pragma unroll
    for (int r = 0; r < 8; r++) {
        float2 p0 = upk(acc[r][0]), p1 = upk(acc[r][1]);
        float2 p2 = upk(acc[r][2]), p3 = upk(acc[r][3]);
        float4 o0, o1;
        o0.x = fmaxf(p0.x, 0.f); o0.y = fmaxf(p0.y, 0.f);
        o0.z = fmaxf(p1.x, 0.f); o0.w = fmaxf(p1.y, 0.f);
        o1.x = fmaxf(p2.x, 0.f); o1.y = fmaxf(p2.y, 0.f);
        o1.z = fmaxf(p3.x, 0.f); o1.w = fmaxf(p3.y, 0.f);
        int row = row0 + ty * 8 + r;
        *(float4*)(g_x2 + row * DN + col0 + tx * 8) = o0;
        *(float4*)(g_x2 + row * DN + col0 + tx * 8 + 4) = o1;
    }
}

// ------------------- output head: [8192,512]@[512,1] -----------------------
__global__ void k_out(const float* __restrict__ W, const float* __restrict__ b,
                      float* __restrict__ out) {
    int g = blockIdx.x * 8 + (threadIdx.x >> 5);
    int lane = threadIdx.x & 31;
    const float4* x4 = (const float4*)(g_x2 + g * DN);
    const float4* w4 = (const float4*)W;
    float s = 0.f;
    #pragma unroll
    for (int i = 0; i < 4; i++) {
        float4 x = x4[lane + i * 32], w = w4[lane + i * 32];
        s += x.x * w.x + x.y * w.y + x.z * w.z + x.w * w.w;
    }
    #pragma unroll
    for (int o = 16; o; o >>= 1) s += __shfl_xor_sync(0xffffffffu, s, o);
    if (lane == 0) out[g] = s + b[0];
}

// ------------------- launch -------------------------------------------------
extern "C" void kernel_launch(void* const* d_in, const int* in_sizes, int n_in,
                              void* d_out, int out_size) {
    const float* x_mol = (const float*)d_in[0];
    const float* x_add = (const float*)d_in[1];
    const int*   esrc  = (const int*)d_in[2];
    const int*   edst  = (const int*)d_in[3];
    const int*   gid   = (const int*)d_in[4];
    const float* gW    = (const float*)d_in[5];
    const float* gb    = (const float*)d_in[6];
    const float* d1W   = (const float*)d_in[7];
    const float* d1b   = (const float*)d_in[8];
    const float* d2W   = (const float*)d_in[9];
    const float* d2b   = (const float*)d_in[10];
    const float* oW    = (const float*)d_in[11];
    const float* ob    = (const float*)d_in[12];
    float* out = (float*)d_out;

    void* p_degcnt = nullptr; void* p_r = nullptr;
    cudaGetSymbolAddress(&p_degcnt, g_degcnt);
    cudaGetSymbolAddress(&p_r, g_r);

    // CSR build (degrees + norms reused across all 3 GNN layers)
    cudaMemsetAsync(p_degcnt, 0, NN * sizeof(int));
    k_hist<<<2048, 512>>>(edst);
    k_scanA<<<512, 512>>>();
    k_scanB<<<1, 512>>>();
    k_scanC<<<512, 512>>>();
    k_fill<<<2048, 512>>>(esrc, edst);

    // readout buffer: zeros + adduct tail (layer-3 agg scatters into it)
    cudaMemsetAsync(p_r, 0, NG * (U + AD) * sizeof(float));
    k_adduct<<<NG * AD / 256, 256>>>(x_add);

    // 3 GCN layers: transform (GEMM) then gather-aggregate (no atomics)
    k_gemm<<<NN / 256, 256>>>(x_mol, gW + 0 * U * U, gb + 0 * U);
    k_agg<false><<<NN / 16, 256>>>(gid);
    k_gemm<<<NN / 256, 256>>>(nullptr, gW + 1 * U * U, gb + 1 * U);
    k_agg<false><<<NN / 16, 256>>>(gid);
    k_gemm<<<NN / 256, 256>>>(nullptr, gW + 2 * U * U, gb + 2 * U);
    k_agg<true><<<NN / 16, 256>>>(gid);   // fused relu + readout scatter

    // MLP head
    k_d1<<<512, 256>>>(d1W, d1b);
    k_d2<<<256, 256>>>(d2W, d2b);
    k_out<<<NG / 8, 256>>>(oW, ob, out);
}